// round 6
// baseline (speedup 1.0000x reference)
#include <cuda_runtime.h>

// SinabsLIFModel: 3x (Linear + LIF scan), B=256, T=4096, widths 16->16->32->10.
// Strategy:
//  - Per layer: fused row-dot + per-(b,neuron) LIF scan.
//  - T split into 8 chunks of 512 with a 320-step warm-up replay (alpha^320 ~ 1e-7,
//    so chunk-start state error is far below any spike-decision margin).
//  - Intermediates (spike counts) stored as u8 in __device__ scratch (L2-resident).
//  - Layers 2/3: all-zero 64-step input subchunks detected at staging and collapsed
//    to v *= alpha^64 (exact: with zero input and v<1 invariant, no spikes possible).
//  - Layer 1 dot uses packed fma.rn.f32x2 (2 MACs/instr vs FFMA rt=2).

#define BATCH 256
#define TSTEPS 4096
#define TC 512
#define NCH 8
#define WARM 320
#define SUB 64

#define ALPHA   0.9512294245007140f   /* exp(-1/20) */
#define ALPHA64 0.0407622039784f      /* exp(-64/20) */

__device__ unsigned char g_s1[BATCH * TSTEPS * 16];
__device__ unsigned char g_s2[BATCH * TSTEPS * 32];

static __device__ __forceinline__ unsigned long long pk2(float lo, float hi) {
    unsigned long long r;
    asm("mov.b64 %0, {%1, %2};" : "=l"(r) : "f"(lo), "f"(hi));
    return r;
}
static __device__ __forceinline__ unsigned long long ffma2(unsigned long long a,
                                                           unsigned long long b,
                                                           unsigned long long c) {
    unsigned long long d;
    asm("fma.rn.f32x2 %0, %1, %2, %3;" : "=l"(d) : "l"(a), "l"(b), "l"(c));
    return d;
}
static __device__ __forceinline__ unsigned long long fadd2(unsigned long long a,
                                                           unsigned long long b) {
    unsigned long long d;
    asm("add.rn.f32x2 %0, %1, %2;" : "=l"(d) : "l"(a), "l"(b));
    return d;
}
static __device__ __forceinline__ float hsum2(unsigned long long a) {
    float lo, hi;
    asm("mov.b64 {%0, %1}, %2;" : "=f"(lo), "=f"(hi) : "l"(a));
    return lo + hi;
}

// ---------------------------------------------------------------------------
// Layer 1: x[B,T,16] f32 @ w1[16,16] -> LIF -> s1[B,T,16] u8
// block: 128 threads = 8 batches x 16 neurons.  grid: (B/8, NCH)
// ---------------------------------------------------------------------------
__global__ void __launch_bounds__(128) k_layer1(const float* __restrict__ x,
                                                const float* __restrict__ w1) {
    const int b0 = blockIdx.x * 8;
    const int chunk = blockIdx.y;
    const int t0 = chunk * TC;
    const int warm = chunk ? WARM : 0;
    const int tstart = t0 - warm;
    const int nsub = (warm + TC) / SUB;

    __shared__ __align__(16) float sh_in[8 * 1028];             // stride 1028 f = 257 float4 (pad)
    __shared__ unsigned long long sh_out[8 * 132];              // stride 1056 B (1024 data + pad)

    const int tid = threadIdx.x;
    const int bb = tid >> 4;
    const int j = tid & 15;

    unsigned long long wp[8];
    {
        const float onem = 1.0f - ALPHA;
#pragma unroll
        for (int k = 0; k < 8; k++)
            wp[k] = pk2(onem * w1[j * 16 + 2 * k], onem * w1[j * 16 + 2 * k + 1]);
    }

    float v = 0.0f;
    const unsigned long long Z2 = 0ull;

    for (int sub = 0; sub < nsub; sub++) {
        const int ts = tstart + sub * SUB;
        __syncthreads();
        {   // cooperative stage: 8 rows x 64 t x 16 c floats (coalesced float4)
            const float4* src = (const float4*)x;
            float4* dst = (float4*)sh_in;
#pragma unroll
            for (int i = 0; i < 16; i++) {
                int idx = tid + i * 128;   // 0..2047
                int r = idx >> 8;
                int o = idx & 255;
                dst[r * 257 + o] = src[((b0 + r) * TSTEPS + ts) * 4 + o];
            }
        }
        __syncthreads();
        const bool emit = (ts >= t0);
        const unsigned long long* xr = (const unsigned long long*)(sh_in + bb * 1028);
        unsigned char* orow = ((unsigned char*)sh_out) + bb * 1056 + j;
#pragma unroll 4
        for (int tt = 0; tt < SUB; tt++) {
            const unsigned long long* xt = xr + tt * 8;
            unsigned long long a0 = ffma2(xt[0], wp[0], Z2);
            unsigned long long a1 = ffma2(xt[1], wp[1], Z2);
            unsigned long long a2 = ffma2(xt[2], wp[2], Z2);
            unsigned long long a3 = ffma2(xt[3], wp[3], Z2);
            a0 = ffma2(xt[4], wp[4], a0);
            a1 = ffma2(xt[5], wp[5], a1);
            a2 = ffma2(xt[6], wp[6], a2);
            a3 = ffma2(xt[7], wp[7], a3);
            a0 = fadd2(a0, a1);
            a2 = fadd2(a2, a3);
            a0 = fadd2(a0, a2);
            float h = hsum2(a0);                 // (1-alpha) already folded into weights
            v = fmaf(ALPHA, v, h);
            float s = fmaxf(floorf(v), 0.0f);    // MultiSpike, threshold = 1
            v -= s;                               // membrane subtract
            orow[tt * 16] = (unsigned char)s;
        }
        if (emit) {
            __syncwarp();
            const int wid = tid >> 5, ln = tid & 31;   // warp w owns rows 2w, 2w+1
#pragma unroll
            for (int k = 0; k < 8; k++) {
                int idx = ln + k * 32;    // 0..255
                int r = 2 * wid + (idx >> 7);
                int o = idx & 127;
                ((unsigned long long*)(g_s1 + ((b0 + r) * TSTEPS + ts) * 16))[o] =
                    sh_out[r * 132 + o];
            }
        }
    }
}

// ---------------------------------------------------------------------------
// Layer 2: s1[B,T,16] u8 @ w2[32,16] -> LIF -> s2[B,T,32] u8
// block: 128 threads = 4 batches x 32 neurons (warp == one batch -> uniform fast path)
// ---------------------------------------------------------------------------
__global__ void __launch_bounds__(128) k_layer2(const float* __restrict__ w2) {
    const int b0 = blockIdx.x * 4;
    const int chunk = blockIdx.y;
    const int t0 = chunk * TC;
    const int warm = chunk ? WARM : 0;
    const int tstart = t0 - warm;
    const int nsub = (warm + TC) / SUB;

    __shared__ __align__(16) unsigned int sh_in[4 * 260];       // 1024 B data + 16 pad per row
    __shared__ unsigned long long sh_out[4 * 258];              // 2048 B data + 16 pad per row
    __shared__ int sh_flag[4];
    __shared__ int sh_oflag[4];

    const int tid = threadIdx.x;
    const int bb = tid >> 5;
    const int j = tid & 31;

    float wr[16];
    {
        const float onem = 1.0f - ALPHA;
#pragma unroll
        for (int c = 0; c < 16; c++) wr[c] = onem * w2[j * 16 + c];
    }

    float v = 0.0f;

    for (int sub = 0; sub < nsub; sub++) {
        const int ts = tstart + sub * SUB;
        __syncthreads();
        {   // stage: warp bb loads its own row (64 int4), OR-detect zeros
            const int4* src = (const int4*)(g_s1 + ((b0 + bb) * TSTEPS + ts) * 16);
            int4 a = src[j];
            int4 b = src[j + 32];
            ((int4*)sh_in)[bb * 65 + j] = a;
            ((int4*)sh_in)[bb * 65 + j + 32] = b;
            unsigned int orv = (unsigned)(a.x | a.y | a.z | a.w | b.x | b.y | b.z | b.w);
            int nz = __any_sync(0xffffffffu, orv != 0u);
            if (j == 0) sh_flag[bb] = nz;
        }
        __syncthreads();
        const bool emit = (ts >= t0);
        if (sh_flag[bb] == 0) {
            // zero input for 64 steps: v just decays; v<1 invariant => no spikes
            v *= ALPHA64;
            if (j == 0) sh_oflag[bb] = 0;
        } else {
            if (j == 0) sh_oflag[bb] = 1;
            const unsigned int* xr = sh_in + bb * 260;
            unsigned char* orow = ((unsigned char*)sh_out) + bb * 2064 + j;
            for (int tt = 0; tt < SUB; tt++) {
                unsigned int p0 = xr[tt * 4 + 0], p1 = xr[tt * 4 + 1];
                unsigned int p2 = xr[tt * 4 + 2], p3 = xr[tt * 4 + 3];
                float h = 0.0f;
                if ((p0 | p1 | p2 | p3) != 0u) {
                    unsigned int p[4] = {p0, p1, p2, p3};
#pragma unroll
                    for (int q = 0; q < 4; q++) {
                        h = fmaf((float)(p[q] & 255u),         wr[q * 4 + 0], h);
                        h = fmaf((float)((p[q] >> 8) & 255u),  wr[q * 4 + 1], h);
                        h = fmaf((float)((p[q] >> 16) & 255u), wr[q * 4 + 2], h);
                        h = fmaf((float)(p[q] >> 24),          wr[q * 4 + 3], h);
                    }
                }
                v = fmaf(ALPHA, v, h);
                float s = fmaxf(floorf(v), 0.0f);
                v -= s;
                orow[tt * 32] = (unsigned char)s;
            }
        }
        if (emit) {
            __syncwarp();
            unsigned long long* dst =
                (unsigned long long*)(g_s2 + ((b0 + bb) * TSTEPS + ts) * 32);
            if (sh_oflag[bb] == 0) {
#pragma unroll
                for (int k = 0; k < 8; k++) dst[j + k * 32] = 0ull;
            } else {
                const unsigned long long* sr = sh_out + bb * 258;
#pragma unroll
                for (int k = 0; k < 8; k++) dst[j + k * 32] = sr[j + k * 32];
            }
        }
    }
}

// ---------------------------------------------------------------------------
// Layer 3: s2[B,T,32] u8 @ w3[10,32] -> LIF -> out[B,T,10] f32
// block: 128 threads = 4 batches x 32 lanes (lanes 0..9 compute; all lanes stage/flush)
// ---------------------------------------------------------------------------
__global__ void __launch_bounds__(128) k_layer3(const float* __restrict__ w3,
                                                float* __restrict__ out) {
    const int b0 = blockIdx.x * 4;
    const int chunk = blockIdx.y;
    const int t0 = chunk * TC;
    const int warm = chunk ? WARM : 0;
    const int tstart = t0 - warm;
    const int nsub = (warm + TC) / SUB;

    __shared__ __align__(16) unsigned int sh_in[4 * 516];       // 2048 B data + 16 pad per row
    __shared__ float sh_outf[4 * 644];                          // 640 f data + 4 pad per row
    __shared__ int sh_flag[4];
    __shared__ int sh_oflag[4];

    const int tid = threadIdx.x;
    const int bb = tid >> 5;
    const int j = tid & 31;

    float wr[32];
    if (j < 10) {
        const float onem = 1.0f - ALPHA;
#pragma unroll
        for (int c = 0; c < 32; c++) wr[c] = onem * w3[j * 32 + c];
    }

    float v = 0.0f;

    for (int sub = 0; sub < nsub; sub++) {
        const int ts = tstart + sub * SUB;
        __syncthreads();
        {   // stage: warp bb loads its own row (128 int4), OR-detect zeros
            const int4* src = (const int4*)(g_s2 + ((b0 + bb) * TSTEPS + ts) * 32);
            unsigned int orv = 0u;
#pragma unroll
            for (int k = 0; k < 4; k++) {
                int4 a = src[j + 32 * k];
                ((int4*)sh_in)[bb * 129 + j + 32 * k] = a;
                orv |= (unsigned)(a.x | a.y | a.z | a.w);
            }
            int nz = __any_sync(0xffffffffu, orv != 0u);
            if (j == 0) sh_flag[bb] = nz;
        }
        __syncthreads();
        const bool emit = (ts >= t0);
        if (sh_flag[bb] == 0) {
            if (j < 10) v *= ALPHA64;
            if (j == 0) sh_oflag[bb] = 0;
        } else {
            if (j == 0) sh_oflag[bb] = 1;
            if (j < 10) {
                const unsigned int* xr = sh_in + bb * 516;
                float* orow = sh_outf + bb * 644;
                for (int tt = 0; tt < SUB; tt++) {
                    unsigned int p[8];
                    unsigned int nzr = 0u;
#pragma unroll
                    for (int q = 0; q < 8; q++) { p[q] = xr[tt * 8 + q]; nzr |= p[q]; }
                    float h = 0.0f;
                    if (nzr) {
#pragma unroll
                        for (int q = 0; q < 8; q++) {
                            h = fmaf((float)(p[q] & 255u),         wr[q * 4 + 0], h);
                            h = fmaf((float)((p[q] >> 8) & 255u),  wr[q * 4 + 1], h);
                            h = fmaf((float)((p[q] >> 16) & 255u), wr[q * 4 + 2], h);
                            h = fmaf((float)(p[q] >> 24),          wr[q * 4 + 3], h);
                        }
                    }
                    v = fmaf(ALPHA, v, h);
                    float s = fmaxf(floorf(v), 0.0f);
                    v -= s;
                    orow[tt * 10 + j] = s;
                }
            }
        }
        if (emit) {
            __syncwarp();
            float* dst = out + ((b0 + bb) * TSTEPS + ts) * 10;   // 640 contiguous f32
            if (sh_oflag[bb] == 0) {
#pragma unroll
                for (int k = 0; k < 20; k++) dst[j + k * 32] = 0.0f;
            } else {
                const float* sr = sh_outf + bb * 644;
#pragma unroll
                for (int k = 0; k < 20; k++) dst[j + k * 32] = sr[j + k * 32];
            }
        }
    }
}

extern "C" void kernel_launch(void* const* d_in, const int* in_sizes, int n_in,
                              void* d_out, int out_size) {
    const float* data = (const float*)d_in[0];   // [256,4096,16]
    const float* w1 = (const float*)d_in[1];     // [16,16]
    const float* w2 = (const float*)d_in[2];     // [32,16]
    const float* w3 = (const float*)d_in[3];     // [10,32]
    float* out = (float*)d_out;                  // [256,4096,10]

    k_layer1<<<dim3(BATCH / 8, NCH), 128>>>(data, w1);
    k_layer2<<<dim3(BATCH / 4, NCH), 128>>>(w2);
    k_layer3<<<dim3(BATCH / 4, NCH), 128>>>(w3, out);
}